// round 14
// baseline (speedup 1.0000x reference)
#include <cuda_runtime.h>

#define BB 2
#define NQv 1024
#define NKv 1024
#define DD 512
#define HH 32
#define NPROJ 128      // proj units: 64 row-tiles x 2 tensors
#define NTILE 1024     // score tiles: B * (NQ/64) * (NK/32)
#define GMAX 512       // target grid (2 tiles per block, perfectly balanced)

// Scratch + coordination (no cudaMalloc allowed).
__device__ __align__(16) float g_hk[BB * NKv * HH];
__device__ __align__(16) float g_hq[BB * NQv * HH];
__device__ unsigned g_epoch = 0;   // monotonic launch-id tickets
__device__ unsigned g_bar   = 0;   // monotonic barrier arrivals

__device__ __forceinline__ float tanh_fast(float x) {
    float y; asm("tanh.approx.f32 %0, %1;" : "=f"(y) : "f"(x)); return y;
}

__global__ __launch_bounds__(256, 4) void fused_kernel(
    const float* __restrict__ keys, const float* __restrict__ queries,
    const float* __restrict__ W1, const float* __restrict__ b1,
    const float* __restrict__ W2, const float* __restrict__ b2,
    float* __restrict__ out)
{
    __shared__ float as[32][128];    // proj A chunk (16 KB)
    __shared__ float ws[128][32];    // proj W chunk (16 KB)
    __shared__ float hqs[64][32];    // score q tile (8 KB)
    __shared__ float hks[32][33];    // score k tile, padded (4.2 KB)
    __shared__ float w2s[32];
    __shared__ unsigned sh_L;

    const int tid  = threadIdx.x;
    const int h    = tid & 31;
    const int warp = tid >> 5;
    const unsigned G = gridDim.x;

    if (tid == 0) sh_L = atomicAdd(&g_epoch, 1u) / G;
    __syncthreads();
    const unsigned L = sh_L;

    // ---------------- Phase 1: projection (STATIC assignment) -------------
    for (unsigned u = blockIdx.x; u < NPROJ; u += G) {
        const int z    = (int)(u >> 6);
        const int row0 = (int)(u & 63) * 32;
        const float* __restrict__ src = z ? queries : keys;

        float acc0 = 0.f, acc1 = 0.f, acc2 = 0.f, acc3 = 0.f;

        for (int c = 0; c < 4; ++c) {
            {
                const float4* __restrict__ ag =
                    (const float4*)(src + (size_t)row0 * DD + c * 128);
                float4* av = (float4*)&as[0][0];
                #pragma unroll
                for (int i = 0; i < 4; ++i) {
                    const int idx = tid + i * 256;
                    av[idx] = __ldg(&ag[(size_t)(idx >> 5) * (DD / 4) + (idx & 31)]);
                }
                const float4* __restrict__ wg =
                    (const float4*)(W1 + (size_t)(z * DD + c * 128) * HH);
                float4* wv = (float4*)&ws[0][0];
                #pragma unroll
                for (int i = 0; i < 4; ++i)
                    wv[tid + i * 256] = __ldg(&wg[tid + i * 256]);
            }
            __syncthreads();

            #pragma unroll 8
            for (int d4 = 0; d4 < 32; ++d4) {
                const float4 a0 = *(const float4*)&as[4 * warp + 0][d4 * 4];
                const float4 a1 = *(const float4*)&as[4 * warp + 1][d4 * 4];
                const float4 a2 = *(const float4*)&as[4 * warp + 2][d4 * 4];
                const float4 a3 = *(const float4*)&as[4 * warp + 3][d4 * 4];
                const float w0  = ws[d4 * 4 + 0][h];
                const float w1v = ws[d4 * 4 + 1][h];
                const float w2v = ws[d4 * 4 + 2][h];
                const float w3v = ws[d4 * 4 + 3][h];
                acc0 = fmaf(a0.x, w0, acc0); acc0 = fmaf(a0.y, w1v, acc0);
                acc0 = fmaf(a0.z, w2v, acc0); acc0 = fmaf(a0.w, w3v, acc0);
                acc1 = fmaf(a1.x, w0, acc1); acc1 = fmaf(a1.y, w1v, acc1);
                acc1 = fmaf(a1.z, w2v, acc1); acc1 = fmaf(a1.w, w3v, acc1);
                acc2 = fmaf(a2.x, w0, acc2); acc2 = fmaf(a2.y, w1v, acc2);
                acc2 = fmaf(a2.z, w2v, acc2); acc2 = fmaf(a2.w, w3v, acc2);
                acc3 = fmaf(a3.x, w0, acc3); acc3 = fmaf(a3.y, w1v, acc3);
                acc3 = fmaf(a3.z, w2v, acc3); acc3 = fmaf(a3.w, w3v, acc3);
            }
            __syncthreads();
        }

        const float bias = (z == 0) ? __ldg(&b1[h]) : 0.f;
        float* __restrict__ dst = (z == 0) ? g_hk : g_hq;
        const int r0 = row0 + 4 * warp;
        dst[(size_t)(r0 + 0) * HH + h] = acc0 + bias;
        dst[(size_t)(r0 + 1) * HH + h] = acc1 + bias;
        dst[(size_t)(r0 + 2) * HH + h] = acc2 + bias;
        dst[(size_t)(r0 + 3) * HH + h] = acc3 + bias;
    }

    // ----------------------- Grid barrier (one-shot) -----------------------
    __threadfence();
    __syncthreads();
    if (tid == 0) {
        atomicAdd(&g_bar, 1u);
        const unsigned tgt = (L + 1u) * G;
        while (*(volatile unsigned*)&g_bar < tgt) __nanosleep(64);
    }
    __syncthreads();
    __threadfence();

    // ---------------- Phase 2: scoring (STATIC, 2 tiles/block) ------------
    if (tid < 32) w2s[tid] = W2[tid];
    const float bias2 = *b2;
    const int kk = (tid & 15) * 2;
    const int qq = (tid >> 4) * 4;

    for (unsigned t = blockIdx.x; t < NTILE; t += G) {
        const int b   = (int)(t >> 9);
        const int rem = (int)(t & 511);
        const int q0  = (rem >> 5) * 64;
        const int k0  = (rem & 31) * 32;

        __syncthreads();   // WAR: previous tile's compute done before restage
        {
            const float4* hq_g =
                (const float4*)(g_hq + (size_t)(b * NQv + q0) * HH);
            float4* hqv = (float4*)&hqs[0][0];
            hqv[tid]       = hq_g[tid];
            hqv[tid + 256] = hq_g[tid + 256];
            const float* hk_g = g_hk + (size_t)(b * NKv + k0) * HH;
            #pragma unroll
            for (int it = 0; it < 4; ++it) {
                const int i = tid + it * 256;
                hks[i >> 5][i & 31] = hk_g[i];
            }
        }
        __syncthreads();

        float a00 = 0.f, a01 = 0.f, a10 = 0.f, a11 = 0.f;
        float a20 = 0.f, a21 = 0.f, a30 = 0.f, a31 = 0.f;

        #pragma unroll
        for (int hh = 0; hh < HH; ++hh) {
            const float w   = w2s[hh];
            const float bk0 = hks[kk][hh];
            const float bk1 = hks[kk + 1][hh];
            const float q0v = hqs[qq + 0][hh];
            const float q1v = hqs[qq + 1][hh];
            const float q2v = hqs[qq + 2][hh];
            const float q3v = hqs[qq + 3][hh];
            a00 = fmaf(w, tanh_fast(q0v + bk0), a00);
            a01 = fmaf(w, tanh_fast(q0v + bk1), a01);
            a10 = fmaf(w, tanh_fast(q1v + bk0), a10);
            a11 = fmaf(w, tanh_fast(q1v + bk1), a11);
            a20 = fmaf(w, tanh_fast(q2v + bk0), a20);
            a21 = fmaf(w, tanh_fast(q2v + bk1), a21);
            a30 = fmaf(w, tanh_fast(q3v + bk0), a30);
            a31 = fmaf(w, tanh_fast(q3v + bk1), a31);
        }

        float* __restrict__ o =
            out + (size_t)(b * NQv + q0 + qq) * NKv + k0 + kk;
        *(float2*)(o + 0 * NKv) = make_float2(a00 + bias2, a01 + bias2);
        *(float2*)(o + 1 * NKv) = make_float2(a10 + bias2, a11 + bias2);
        *(float2*)(o + 2 * NKv) = make_float2(a20 + bias2, a21 + bias2);
        *(float2*)(o + 3 * NKv) = make_float2(a30 + bias2, a31 + bias2);
    }
}

extern "C" void kernel_launch(void* const* d_in, const int* in_sizes, int n_in,
                              void* d_out, int out_size)
{
    const float* keys    = (const float*)d_in[0];
    const float* queries = (const float*)d_in[1];
    const float* W1      = (const float*)d_in[2];
    const float* b1      = (const float*)d_in[3];
    const float* W2      = (const float*)d_in[4];
    const float* b2      = (const float*)d_in[5];
    float* out = (float*)d_out;

    // Grid: as close to GMAX as co-residency allows (barrier-safe).
    int dev = 0;
    cudaGetDevice(&dev);
    int sms = 148;
    cudaDeviceGetAttribute(&sms, cudaDevAttrMultiProcessorCount, dev);
    int occ = 1;
    cudaOccupancyMaxActiveBlocksPerMultiprocessor(&occ, fused_kernel, 256, 0);
    if (occ < 1) occ = 1;
    int grid = sms * occ;
    if (grid > GMAX) grid = GMAX;

    fused_kernel<<<grid, 256>>>(keys, queries, W1, b1, W2, b2, out);
}

// round 16
// speedup vs baseline: 1.4345x; 1.4345x over previous
#include <cuda_runtime.h>

#define BB 2
#define NQv 1024
#define NKv 1024
#define DD 512
#define HH 32

// Scratch (no cudaMalloc allowed). Raw f32 projections.
__device__ __align__(16) float g_hk[BB * NKv * HH];   // keys@W1[:D] + b1
__device__ __align__(16) float g_hq[BB * NQv * HH];   // queries@W1[D:]

__device__ __forceinline__ float tanh_fast(float x) {
    float y; asm("tanh.approx.f32 %0, %1;" : "=f"(y) : "f"(x)); return y;
}
__device__ __forceinline__ unsigned smem_u32(const void* p) {
    return (unsigned)__cvta_generic_to_shared(p);
}
__device__ __forceinline__ void cp16(unsigned dst, const void* src) {
    asm volatile("cp.async.cg.shared.global [%0], [%1], 16;" :: "r"(dst), "l"(src));
}
__device__ __forceinline__ void cp_commit() {
    asm volatile("cp.async.commit_group;");
}
template <int N> __device__ __forceinline__ void cp_wait() {
    asm volatile("cp.async.wait_group %0;" :: "n"(N));
}

// ---------------------------------------------------------------------------
// Projection (R13 cp.async double buffer, ORIGINAL verified ordering):
// C[2048,32] = A[2048,512]@W[512,32] per tensor. Grid (64,2) = 128 blocks,
// 256 thr, 32 rows/block, thread = 4 rows x 1 h, K in 8 chunks of 64 d.
// Protocol per chunk: stage(c+1) -> commit -> wait(c landed, per-thread)
// -> __syncthreads (publish cross-thread) -> compute(c) -> __syncthreads
// (WAR before restaging the buffer). The barrier AFTER the wait is what
// makes other threads' cp.async data visible — do not reorder.
// ---------------------------------------------------------------------------
__global__ __launch_bounds__(256) void proj_kernel(
    const float* __restrict__ keys, const float* __restrict__ queries,
    const float* __restrict__ W1, const float* __restrict__ b1)
{
    __shared__ __align__(16) float as[2][32][64];   // A chunks (2 x 8 KB)
    __shared__ __align__(16) float ws[2][64][32];   // W chunks (2 x 8 KB)

    const int z    = blockIdx.y;
    const int tid  = threadIdx.x;
    const int h    = tid & 31;
    const int warp = tid >> 5;
    const int row0 = blockIdx.x * 32;
    const float* __restrict__ src = z ? queries : keys;

    // Per-thread staging geometry (constant across chunks).
    const int ar0 = tid >> 4,         aj0 = tid & 15;
    const int ar1 = (tid + 256) >> 4, aj1 = tid & 15;
    const int wd0 = tid >> 3,         wj0 = tid & 7;
    const int wd1 = (tid + 256) >> 3, wj1 = tid & 7;
    const float4* __restrict__ ag = (const float4*)src;
    const float4* __restrict__ wg =
        (const float4*)(W1 + (size_t)(z * DD) * HH);

    auto stage = [&](int c, int buf) {
        cp16(smem_u32(&as[buf][ar0][aj0 * 4]),
             ag + (size_t)(row0 + ar0) * (DD / 4) + c * 16 + aj0);
        cp16(smem_u32(&as[buf][ar1][aj1 * 4]),
             ag + (size_t)(row0 + ar1) * (DD / 4) + c * 16 + aj1);
        cp16(smem_u32(&ws[buf][wd0][wj0 * 4]), wg + (size_t)c * 512 + tid);
        cp16(smem_u32(&ws[buf][wd1][wj1 * 4]), wg + (size_t)c * 512 + tid + 256);
    };

    float acc0 = 0.f, acc1 = 0.f, acc2 = 0.f, acc3 = 0.f;

    stage(0, 0);
    cp_commit();

    #pragma unroll
    for (int c = 0; c < 8; ++c) {
        const int buf = c & 1;
        if (c < 7) {
            stage(c + 1, buf ^ 1);
            cp_commit();
            cp_wait<1>();       // chunk c complete (per-thread)
        } else {
            cp_wait<0>();
        }
        __syncthreads();        // publish: all threads' chunk-c data visible

        #pragma unroll
        for (int d4 = 0; d4 < 16; ++d4) {
            const float4 a0 = *(const float4*)&as[buf][4 * warp + 0][d4 * 4];
            const float4 a1 = *(const float4*)&as[buf][4 * warp + 1][d4 * 4];
            const float4 a2 = *(const float4*)&as[buf][4 * warp + 2][d4 * 4];
            const float4 a3 = *(const float4*)&as[buf][4 * warp + 3][d4 * 4];
            const float w0  = ws[buf][d4 * 4 + 0][h];
            const float w1v = ws[buf][d4 * 4 + 1][h];
            const float w2v = ws[buf][d4 * 4 + 2][h];
            const float w3v = ws[buf][d4 * 4 + 3][h];
            acc0 = fmaf(a0.x, w0, acc0); acc0 = fmaf(a0.y, w1v, acc0);
            acc0 = fmaf(a0.z, w2v, acc0); acc0 = fmaf(a0.w, w3v, acc0);
            acc1 = fmaf(a1.x, w0, acc1); acc1 = fmaf(a1.y, w1v, acc1);
            acc1 = fmaf(a1.z, w2v, acc1); acc1 = fmaf(a1.w, w3v, acc1);
            acc2 = fmaf(a2.x, w0, acc2); acc2 = fmaf(a2.y, w1v, acc2);
            acc2 = fmaf(a2.z, w2v, acc2); acc2 = fmaf(a2.w, w3v, acc2);
            acc3 = fmaf(a3.x, w0, acc3); acc3 = fmaf(a3.y, w1v, acc3);
            acc3 = fmaf(a3.z, w2v, acc3); acc3 = fmaf(a3.w, w3v, acc3);
        }
        __syncthreads();        // WAR: buffer free for chunk c+2's stage
    }

    const float bias = (z == 0) ? __ldg(&b1[h]) : 0.f;
    float* __restrict__ dst = (z == 0) ? g_hk : g_hq;
    const int r0 = row0 + 4 * warp;
    dst[(size_t)(r0 + 0) * HH + h] = acc0 + bias;
    dst[(size_t)(r0 + 1) * HH + h] = acc1 + bias;
    dst[(size_t)(r0 + 2) * HH + h] = acc2 + bias;
    dst[(size_t)(r0 + 3) * HH + h] = acc3 + bias;
}

// ---------------------------------------------------------------------------
// Scoring (best measured 20.35us config): 64q x 32k tile, 256 thr, thread =
// 4q x 2k, f32 tanh on XU pipe. Accumulators initialized with the output
// bias (pure algebra; saves 8 epilogue FADDs).
// ---------------------------------------------------------------------------
__global__ __launch_bounds__(256) void score_kernel(
    const float* __restrict__ W2, const float* __restrict__ b2,
    float* __restrict__ out)
{
    __shared__ float hqs[64][32];
    __shared__ float hks[32][33];
    __shared__ float w2s[32];

    const int b   = blockIdx.z;
    const int q0  = blockIdx.y * 64;
    const int k0  = blockIdx.x * 32;
    const int tid = threadIdx.x;

    {
        const float4* __restrict__ hq_g =
            (const float4*)(g_hq + (size_t)(b * NQv + q0) * HH);
        float4* hqv = (float4*)&hqs[0][0];
        hqv[tid]       = hq_g[tid];
        hqv[tid + 256] = hq_g[tid + 256];
        const float* __restrict__ hk_g = g_hk + (size_t)(b * NKv + k0) * HH;
        #pragma unroll
        for (int it = 0; it < 4; ++it) {
            const int i = tid + it * 256;
            hks[i >> 5][i & 31] = hk_g[i];
        }
        if (tid < 32) w2s[tid] = __ldg(&W2[tid]);
    }
    const float bias = __ldg(b2);
    __syncthreads();

    const int kk = (tid & 15) * 2;
    const int qq = (tid >> 4) * 4;

    float a00 = bias, a01 = bias, a10 = bias, a11 = bias;
    float a20 = bias, a21 = bias, a30 = bias, a31 = bias;

    #pragma unroll
    for (int h = 0; h < HH; ++h) {
        const float w   = w2s[h];
        const float bk0 = hks[kk][h];
        const float bk1 = hks[kk + 1][h];
        const float q0v = hqs[qq + 0][h];
        const float q1v = hqs[qq + 1][h];
        const float q2v = hqs[qq + 2][h];
        const float q3v = hqs[qq + 3][h];
        a00 = fmaf(w, tanh_fast(q0v + bk0), a00);
        a01 = fmaf(w, tanh_fast(q0v + bk1), a01);
        a10 = fmaf(w, tanh_fast(q1v + bk0), a10);
        a11 = fmaf(w, tanh_fast(q1v + bk1), a11);
        a20 = fmaf(w, tanh_fast(q2v + bk0), a20);
        a21 = fmaf(w, tanh_fast(q2v + bk1), a21);
        a30 = fmaf(w, tanh_fast(q3v + bk0), a30);
        a31 = fmaf(w, tanh_fast(q3v + bk1), a31);
    }

    float* __restrict__ o =
        out + (size_t)(b * NQv + q0 + qq) * NKv + k0 + kk;
    *(float2*)(o + 0 * NKv) = make_float2(a00, a01);
    *(float2*)(o + 1 * NKv) = make_float2(a10, a11);
    *(float2*)(o + 2 * NKv) = make_float2(a20, a21);
    *(float2*)(o + 3 * NKv) = make_float2(a30, a31);
}

extern "C" void kernel_launch(void* const* d_in, const int* in_sizes, int n_in,
                              void* d_out, int out_size)
{
    const float* keys    = (const float*)d_in[0];
    const float* queries = (const float*)d_in[1];
    const float* W1      = (const float*)d_in[2];
    const float* b1      = (const float*)d_in[3];
    const float* W2      = (const float*)d_in[4];
    const float* b2      = (const float*)d_in[5];
    float* out = (float*)d_out;

    proj_kernel<<<dim3(64, 2, 1), 256>>>(keys, queries, W1, b1);
    score_kernel<<<dim3(NKv / 32, NQv / 64, BB), 256>>>(W2, b2, out);
}